// round 2
// baseline (speedup 1.0000x reference)
#include <cuda_runtime.h>
#include <cuda_bf16.h>

// Problem constants (fixed by the reference).
#define NB 8192   // batch
#define NH 1024   // hidden
#define NO 256    // out features
#define NE 16     // experts

// --- scratch (no allocs allowed) ---
__device__ int g_expert[NB];
__device__ int g_perm[NB];
__device__ int g_counts[NE];
__device__ int g_offsets[NE + 1];
__device__ int g_cursor[NE];

// ---------------- pass 1: zero counters ----------------
__global__ void zero_kernel() {
    int t = threadIdx.x;
    if (t < NE) { g_counts[t] = 0; g_cursor[t] = 0; }
}

// ---------------- pass 2: classify + count ----------------
// NOTE: JAX default config has x64 disabled -> num/c are int32 on device.
__global__ void classify_kernel(const int* __restrict__ num,
                                const int* __restrict__ c,
                                int cmap_n) {
    int i = blockIdx.x * blockDim.x + threadIdx.x;
    if (i < NB) {
        int idx = num[i];
        if (idx < 0) idx = 0;
        if (idx >= cmap_n) idx = cmap_n - 1;
        int e = c[idx] & (NE - 1);    // mask = fault insurance; no-op for in-spec data
        g_expert[i] = e;
        atomicAdd(&g_counts[e], 1);
    }
}

// ---------------- pass 3: tiny prefix sum (16 bins) ----------------
__global__ void prefix_kernel() {
    if (threadIdx.x == 0) {
        int acc = 0;
        g_offsets[0] = 0;
        #pragma unroll
        for (int e = 0; e < NE; e++) {
            acc += g_counts[e];
            g_offsets[e + 1] = acc;
        }
    }
}

// ---------------- pass 4: scatter sample ids into per-expert bins ----------------
__global__ void scatter_kernel() {
    int i = blockIdx.x * blockDim.x + threadIdx.x;
    if (i < NB) {
        int e = g_expert[i];
        int pos = g_offsets[e] + atomicAdd(&g_cursor[e], 1);
        g_perm[pos] = i;
    }
}

// ---------------- pass 5: per-expert tiled GEMM + bias + sigmoid ----------------
// grid = (NO/BN, NB/BM, NE); blocks past an expert's row count exit immediately.
#define BM 64
#define BN 64
#define BK 16

__global__ __launch_bounds__(256, 4)
void gemm_kernel(const float* __restrict__ x,
                 const float* __restrict__ W,
                 const float* __restrict__ bias,
                 float* __restrict__ out) {
    const int e = blockIdx.z;
    const int row0 = g_offsets[e];
    const int rows = g_offsets[e + 1] - row0;
    const int m_start = blockIdx.y * BM;
    if (m_start >= rows) return;
    const int n_start = blockIdx.x * BN;

    __shared__ float As[BK][BM];   // As[k][m] = x[perm[m]][k0+k]
    __shared__ float Bs[BK][BN];   // Bs[k][n] = W[e][n0+n][k0+k]

    const int t  = threadIdx.x;        // 256 threads
    const int tx = t & 15;             // 0..15 -> 4 output cols each
    const int ty = t >> 4;             // 0..15 -> 4 output rows each

    // cooperative-load coords: 64 rows x 4 float4-chunks (= 16 k-values)
    const int lm  = t & 63;            // row within tile
    const int lk4 = t >> 6;            // which float4 along k (0..3)

    const float* Wb = W + (size_t)e * NO * NH;

    const int  xm     = m_start + lm;
    const bool mvalid = (xm < rows);
    const int  xrow   = g_perm[row0 + (mvalid ? xm : 0)];
    const float* xptr = x  + (size_t)xrow * NH + lk4 * 4;
    const float* wptr = Wb + (size_t)(n_start + lm) * NH + lk4 * 4;

    float acc[4][4];
    #pragma unroll
    for (int i = 0; i < 4; i++)
        #pragma unroll
        for (int j = 0; j < 4; j++) acc[i][j] = 0.f;

    for (int k0 = 0; k0 < NH; k0 += BK) {
        float4 xa = mvalid ? *(const float4*)(xptr + k0) : make_float4(0.f, 0.f, 0.f, 0.f);
        float4 wa = *(const float4*)(wptr + k0);
        __syncthreads();   // previous iteration's smem reads done
        As[lk4 * 4 + 0][lm] = xa.x;
        As[lk4 * 4 + 1][lm] = xa.y;
        As[lk4 * 4 + 2][lm] = xa.z;
        As[lk4 * 4 + 3][lm] = xa.w;
        Bs[lk4 * 4 + 0][lm] = wa.x;
        Bs[lk4 * 4 + 1][lm] = wa.y;
        Bs[lk4 * 4 + 2][lm] = wa.z;
        Bs[lk4 * 4 + 3][lm] = wa.w;
        __syncthreads();

        #pragma unroll
        for (int k = 0; k < BK; k++) {
            float a[4], b[4];
            *(float4*)a = *(const float4*)&As[k][ty * 4];
            *(float4*)b = *(const float4*)&Bs[k][tx * 4];
            #pragma unroll
            for (int i = 0; i < 4; i++)
                #pragma unroll
                for (int j = 0; j < 4; j++)
                    acc[i][j] = fmaf(a[i], b[j], acc[i][j]);
        }
    }

    // epilogue: bias + sigmoid, scatter rows through perm
    #pragma unroll
    for (int i = 0; i < 4; i++) {
        const int m = m_start + ty * 4 + i;
        if (m < rows) {
            const int row = g_perm[row0 + m];
            #pragma unroll
            for (int j = 0; j < 4; j++) {
                const int n = n_start + tx * 4 + j;
                const float v = acc[i][j] + bias[e * NO + n];
                out[(size_t)row * NO + n] = 1.f / (1.f + __expf(-v));
            }
        }
    }
}

extern "C" void kernel_launch(void* const* d_in, const int* in_sizes, int n_in,
                              void* d_out, int out_size) {
    const float* x    = (const float*)d_in[0];   // [B, H]
    const float* W    = (const float*)d_in[1];   // [E, O, H]
    const float* bias = (const float*)d_in[2];   // [E, O]
    const int*   num  = (const int*)d_in[3];     // [B]   int32 (JAX x64 disabled)
    const int*   c    = (const int*)d_in[4];     // [CMAP] int32
    float* out = (float*)d_out;                  // [B, O]

    const int cmap_n = in_sizes[4];

    zero_kernel<<<1, 32>>>();
    classify_kernel<<<NB / 256, 256>>>(num, c, cmap_n);
    prefix_kernel<<<1, 32>>>();
    scatter_kernel<<<NB / 256, 256>>>();

    dim3 grid(NO / BN, NB / BM, NE);
    gemm_kernel<<<grid, 256>>>(x, W, bias, out);
}